// round 8
// baseline (speedup 1.0000x reference)
#include <cuda_runtime.h>
#include <cuda_fp16.h>
#include <cstdint>

#define BV 8
#define TV 512
#define DV 2048
#define HV 2048
#define STEPS (BV * TV)
#define R4H (4 * HV)
#define GRID 148
#define JPC 14                     /* hidden units per CTA */
#define ROWS 56                    /* 4*JPC gate-rows per CTA */
#define NTH 256                    /* 8 warps (R5-proven) */
#define LSTM_SMEM (ROWS * HV * 2 + 2 * ROWS * 4)
#define OUTSTRIDE ((size_t)STEPS * HV)

typedef unsigned long long u64t;

__device__ float g_xp[(size_t)STEPS * R4H];
__device__ __align__(16) __half g_hh[2][HV];
__device__ unsigned int g_bar;

#define FFMA2(d, a, b) \
    asm volatile("fma.rn.f32x2 %0, %1, %2, %0;" : "+l"(d) : "l"(a), "l"(b))
#define PACK2(d, s) \
    asm volatile("mov.b64 %0, {%1, %1};" : "=l"(d) : "r"(s))
#define UNPACK2(lo, hi, s) \
    asm volatile("mov.b64 {%0, %1}, %2;" : "=r"(lo), "=r"(hi) : "l"(s))

__device__ __forceinline__ __half2 u2h(unsigned u) {
    return *reinterpret_cast<__half2*>(&u);
}
__device__ __forceinline__ uint4 pack8(float4 f0, float4 f1) {
    uint4 v; __half2 h;
    h = __floats2half2_rn(f0.x, f0.y); v.x = *(unsigned*)&h;
    h = __floats2half2_rn(f0.z, f0.w); v.y = *(unsigned*)&h;
    h = __floats2half2_rn(f1.x, f1.y); v.z = *(unsigned*)&h;
    h = __floats2half2_rn(f1.z, f1.w); v.w = *(unsigned*)&h;
    return v;
}
__device__ __forceinline__ void bar_arrive_release() {
    asm volatile("red.release.gpu.global.add.u32 [%0], %1;"
                 :: "l"(&g_bar), "r"(1u) : "memory");
}
__device__ __forceinline__ void bar_spin_acquire(unsigned tgt) {
    unsigned v;
    do {
        asm volatile("ld.acquire.gpu.global.u32 %0, [%1];"
                     : "=r"(v) : "l"(&g_bar) : "memory");
    } while (v < tgt);
}

// ---------------------------------------------------------------- GEMM (+init)
#define GBK 16
#define GPAD 132
__global__ void __launch_bounds__(256, 2)
gemm_xp(const float* __restrict__ A, const float* __restrict__ Bm,
        const float* __restrict__ bias, const float* __restrict__ h0) {
    __shared__ __align__(16) float Xs[2][GBK][GPAD];
    __shared__ __align__(16) float Ws2[2][GBK][GPAD];
    const int tid = threadIdx.x;

    if (blockIdx.x == 0 && blockIdx.y == 0) {   // reset shared state each launch
        if (tid == 0) g_bar = 0u;
        for (int i = tid; i < HV; i += 256) g_hh[0][i] = __float2half(h0[i]);
    }

    const int m0 = blockIdx.x * 128, n0 = blockIdx.y * 128;
    const int tx = (tid & 15) << 3, ty = (tid >> 4) << 3;
    const int ln = tid >> 1, lk = (tid & 1) << 3;

    const float* Ald = A + (size_t)(n0 + ln) * DV + lk;
    const float* Bld = Bm + (size_t)(m0 + ln) * DV + lk;
    float4 ax = *(const float4*)(Ald), ay = *(const float4*)(Ald + 4);
    float4 bx = *(const float4*)(Bld), by = *(const float4*)(Bld + 4);

    u64t acc2[8][4];
    u64t zero2; PACK2(zero2, 0u);
#pragma unroll
    for (int i = 0; i < 8; ++i)
#pragma unroll
        for (int jp = 0; jp < 4; ++jp) acc2[i][jp] = zero2;

    int buf = 0;
#pragma unroll
    for (int m = 0; m < 4; ++m) {
        Xs[0][lk + m][ln] = (&ax.x)[m];   Xs[0][lk + 4 + m][ln] = (&ay.x)[m];
        Ws2[0][lk + m][ln] = (&bx.x)[m];  Ws2[0][lk + 4 + m][ln] = (&by.x)[m];
    }
    __syncthreads();

    const int NKT = DV / GBK;
    for (int kt = 0; kt < NKT; ++kt) {
        if (kt + 1 < NKT) {
            const float* An = Ald + (kt + 1) * GBK;
            const float* Bn = Bld + (kt + 1) * GBK;
            ax = *(const float4*)(An); ay = *(const float4*)(An + 4);
            bx = *(const float4*)(Bn); by = *(const float4*)(Bn + 4);
        }
#pragma unroll
        for (int kk = 0; kk < GBK; ++kk) {
            float av[8];
            *(float4*)&av[0] = *(const float4*)&Xs[buf][kk][ty];
            *(float4*)&av[4] = *(const float4*)&Xs[buf][kk][ty + 4];
            ulonglong2 q0 = *(const ulonglong2*)&Ws2[buf][kk][tx];
            ulonglong2 q1 = *(const ulonglong2*)&Ws2[buf][kk][tx + 4];
            u64t bv2[4] = {q0.x, q0.y, q1.x, q1.y};
#pragma unroll
            for (int i = 0; i < 8; ++i) {
                u64t a2; PACK2(a2, __float_as_uint(av[i]));
#pragma unroll
                for (int jp = 0; jp < 4; ++jp) FFMA2(acc2[i][jp], a2, bv2[jp]);
            }
        }
        if (kt + 1 < NKT) {
            buf ^= 1;
            __syncthreads();
#pragma unroll
            for (int m = 0; m < 4; ++m) {
                Xs[buf][lk + m][ln] = (&ax.x)[m];   Xs[buf][lk + 4 + m][ln] = (&ay.x)[m];
                Ws2[buf][lk + m][ln] = (&bx.x)[m];  Ws2[buf][lk + 4 + m][ln] = (&by.x)[m];
            }
            __syncthreads();
        }
    }
    float4 bb0 = *(const float4*)(bias + m0 + tx);
    float4 bb1 = *(const float4*)(bias + m0 + tx + 4);
    float bvv[8] = {bb0.x, bb0.y, bb0.z, bb0.w, bb1.x, bb1.y, bb1.z, bb1.w};
#pragma unroll
    for (int i = 0; i < 8; ++i) {
        float o[8];
#pragma unroll
        for (int jp = 0; jp < 4; ++jp) {
            unsigned lo, hi;
            UNPACK2(lo, hi, acc2[i][jp]);
            o[2 * jp]     = __uint_as_float(lo) + bvv[2 * jp];
            o[2 * jp + 1] = __uint_as_float(hi) + bvv[2 * jp + 1];
        }
        float* cp = g_xp + (size_t)(n0 + ty + i) * R4H + m0 + tx;
        *(float4*)cp = *(float4*)&o[0];
        *(float4*)(cp + 4) = *(float4*)&o[4];
    }
}

// ---------------------------------------------------------------- LSTM
__global__ void __launch_bounds__(NTH, 1)
lstm_kernel(const float* __restrict__ c0, const float* __restrict__ W_hh,
            const float* __restrict__ b_hh, float* __restrict__ out) {
    extern __shared__ __align__(16) unsigned char smem_raw[];
    uint4* Wq = reinterpret_cast<uint4*>(smem_raw);
    float* pre_part = reinterpret_cast<float*>(smem_raw + (size_t)ROWS * HV * 2);

    const int tid = threadIdx.x, cta = blockIdx.x;
    const int j0 = cta * JPC;
    int J = HV - j0; if (J > JPC) J = JPC; if (J < 0) J = 0;

    // stage W_hh slice -> SMEM fp16, vectorized (uint4 = 8 halves)
    for (int u = tid; u < ROWS * 256; u += NTH) {
        int rl = u >> 8, rem = u & 255;
        int jl = rl >> 2, gate = rl & 3;
        uint4 v = make_uint4(0, 0, 0, 0);
        if (jl < J) {
            const float* wp = W_hh + ((size_t)gate * HV + j0 + jl) * HV + rem * 8;
            v = pack8(*(const float4*)wp, *(const float4*)(wp + 4));
        }
        Wq[u] = v;
    }

    const int warp = tid >> 5, lane = tid & 31;
    const int grp = warp >> 1, khalf = warp & 1;
    const int kb = khalf << 10;
    const int rbase = grp * JPC;

    float c_val = 0.f, b_r[4] = {0.f, 0.f, 0.f, 0.f};
    if (tid < J) {
        c_val = c0[j0 + tid];
#pragma unroll
        for (int g = 0; g < 4; ++g) b_r[g] = b_hh[g * HV + j0 + tid];
    }
    float xp_r[4] = {0.f, 0.f, 0.f, 0.f};
    if (tid < J) {
#pragma unroll
        for (int g = 0; g < 4; ++g)
            xp_r[g] = __ldcg(&g_xp[(size_t)g * HV + j0 + tid]);
    }
    __syncthreads();

    const size_t wbase = (size_t)rbase * 256 + (size_t)khalf * 128 + lane;
    const __half2 hz = __float2half2_rn(0.f);

    for (int t = 0; t < STEPS; ++t) {
        const int p = t & 1;

        // ---- h (fp16) -> registers: 4x LDG.128 (L2)
        uint4 hq[4];
        {
            const uint4* hb4 = reinterpret_cast<const uint4*>(&g_hh[p][kb]) + lane;
#pragma unroll
            for (int it = 0; it < 4; ++it) hq[it] = __ldcg(hb4 + it * 32);
        }

        __half2 acc[JPC][4];
#pragma unroll
        for (int r = 0; r < JPC; ++r)
#pragma unroll
            for (int s = 0; s < 4; ++s) acc[r][s] = hz;

#pragma unroll
        for (int it = 0; it < 4; ++it) {
#pragma unroll
            for (int r = 0; r < JPC; ++r) {
                uint4 w = Wq[wbase + (size_t)r * 256 + it * 32];
                acc[r][0] = __hfma2(u2h(w.x), u2h(hq[it].x), acc[r][0]);
                acc[r][1] = __hfma2(u2h(w.y), u2h(hq[it].y), acc[r][1]);
                acc[r][2] = __hfma2(u2h(w.z), u2h(hq[it].z), acc[r][2]);
                acc[r][3] = __hfma2(u2h(w.w), u2h(hq[it].w), acc[r][3]);
            }
        }
#pragma unroll
        for (int r = 0; r < JPC; ++r) {
            float2 f0 = __half22float2(acc[r][0]);
            float2 f1 = __half22float2(acc[r][1]);
            float2 f2 = __half22float2(acc[r][2]);
            float2 f3 = __half22float2(acc[r][3]);
            float v = ((f0.x + f0.y) + (f1.x + f1.y)) +
                      ((f2.x + f2.y) + (f3.x + f3.y));
            v += __shfl_xor_sync(~0u, v, 16);
            v += __shfl_xor_sync(~0u, v, 8);
            v += __shfl_xor_sync(~0u, v, 4);
            v += __shfl_xor_sync(~0u, v, 2);
            v += __shfl_xor_sync(~0u, v, 1);
            if (lane == 0) pre_part[khalf * ROWS + rbase + r] = v;
        }
        __syncthreads();   // pre_part ready for warp 0

        const unsigned tgt = (unsigned)(t + 1) * GRID;
        if (warp == 0) {
            float h_n = 0.f, f_t = 0.f, i_t = 0.f;
            if (tid < J) {
                const int rl = tid << 2;
                float pi = xp_r[0] + b_r[0] + pre_part[rl + 0] + pre_part[ROWS + rl + 0];
                float pf = xp_r[1] + b_r[1] + pre_part[rl + 1] + pre_part[ROWS + rl + 1];
                float po = xp_r[2] + b_r[2] + pre_part[rl + 2] + pre_part[ROWS + rl + 2];
                float pg = xp_r[3] + b_r[3] + pre_part[rl + 3] + pre_part[ROWS + rl + 3];
                i_t = __fdividef(1.0f, 1.0f + __expf(-pi));
                f_t = __fdividef(1.0f, 1.0f + __expf(-pf));
                float o_t = __fdividef(1.0f, 1.0f + __expf(-po));
                float g_t = __fdividef(2.0f, 1.0f + __expf(-2.0f * pg)) - 1.0f;
                c_val = c_val * f_t + i_t * g_t;
                float tc = __fdividef(2.0f, 1.0f + __expf(-2.0f * c_val)) - 1.0f;
                h_n = o_t * tc;
                g_hh[p ^ 1][j0 + tid] = __float2half(h_n);   // publish h first
            }
            __syncwarp();
            if (lane == 0) bar_arrive_release();             // release + arrive
            if (tid < J) {                                   // off critical path
                size_t oi = (size_t)t * HV + j0 + tid;
                out[oi] = h_n;
                out[OUTSTRIDE + oi] = f_t;
                out[2 * OUTSTRIDE + oi] = i_t;
                if (t + 1 < STEPS) {
#pragma unroll
                    for (int g = 0; g < 4; ++g)
                        xp_r[g] = __ldcg(&g_xp[(size_t)(t + 1) * R4H + g * HV + j0 + tid]);
                }
            }
        }
        // every warp spins independently (no broadcast syncthreads)
        if (lane == 0) bar_spin_acquire(tgt);
        __syncwarp();
    }
}

extern "C" void kernel_launch(void* const* d_in, const int* in_sizes, int n_in,
                              void* d_out, int out_size) {
    const float* input_ = (const float*)d_in[0];
    const float* h0 = (const float*)d_in[1];
    const float* c0 = (const float*)d_in[2];
    const float* W_ih = (const float*)d_in[3];
    const float* b_ih = (const float*)d_in[4];
    const float* W_hh = (const float*)d_in[5];
    const float* b_hh = (const float*)d_in[6];
    float* out = (float*)d_out;

    static int smem_set = 0;
    if (!smem_set) {
        cudaFuncSetAttribute(lstm_kernel, cudaFuncAttributeMaxDynamicSharedMemorySize,
                             LSTM_SMEM);
        smem_set = 1;
    }

    gemm_xp<<<dim3(R4H / 128, STEPS / 128), 256>>>(input_, W_ih, b_ih, h0);
    lstm_kernel<<<GRID, NTH, LSTM_SMEM>>>(c0, W_hh, b_hh, out);
}

// round 9
// speedup vs baseline: 3.1132x; 3.1132x over previous
#include <cuda_runtime.h>
#include <cuda_fp16.h>
#include <cstdint>

#define BV 8
#define TV 512
#define DV 2048
#define HV 2048
#define STEPS (BV * TV)
#define R4H (4 * HV)
#define GRID 148
#define JPC 14                     /* hidden units per CTA */
#define ROWS 56                    /* 4*JPC gate-rows per CTA */
#define NTH 256                    /* 8 warps (R5-proven) */
#define LSTM_SMEM (ROWS * HV * 2 + 2 * ROWS * 4)
#define OUTSTRIDE ((size_t)STEPS * HV)

typedef unsigned long long u64t;

__device__ float g_xp[(size_t)STEPS * R4H];
__device__ __align__(16) __half g_hh[2][HV];
__device__ unsigned int g_bar;

#define FFMA2(d, a, b) \
    asm volatile("fma.rn.f32x2 %0, %1, %2, %0;" : "+l"(d) : "l"(a), "l"(b))
#define PACK2(d, s) \
    asm volatile("mov.b64 %0, {%1, %1};" : "=l"(d) : "r"(s))
#define UNPACK2(lo, hi, s) \
    asm volatile("mov.b64 {%0, %1}, %2;" : "=r"(lo), "=r"(hi) : "l"(s))

__device__ __forceinline__ __half2 u2h(unsigned u) {
    return *reinterpret_cast<__half2*>(&u);
}
__device__ __forceinline__ uint4 pack8(float4 f0, float4 f1) {
    uint4 v; __half2 h;
    h = __floats2half2_rn(f0.x, f0.y); v.x = *(unsigned*)&h;
    h = __floats2half2_rn(f0.z, f0.w); v.y = *(unsigned*)&h;
    h = __floats2half2_rn(f1.x, f1.y); v.z = *(unsigned*)&h;
    h = __floats2half2_rn(f1.z, f1.w); v.w = *(unsigned*)&h;
    return v;
}

// ---------------------------------------------------------------- GEMM (+init)
#define GBK 16
#define GPAD 132
__global__ void __launch_bounds__(256, 2)
gemm_xp(const float* __restrict__ A, const float* __restrict__ Bm,
        const float* __restrict__ bias, const float* __restrict__ h0) {
    __shared__ __align__(16) float Xs[2][GBK][GPAD];
    __shared__ __align__(16) float Ws2[2][GBK][GPAD];
    const int tid = threadIdx.x;

    if (blockIdx.x == 0 && blockIdx.y == 0) {   // reset shared state each launch
        if (tid == 0) g_bar = 0u;
        for (int i = tid; i < HV; i += 256) g_hh[0][i] = __float2half(h0[i]);
    }

    const int m0 = blockIdx.x * 128, n0 = blockIdx.y * 128;
    const int tx = (tid & 15) << 3, ty = (tid >> 4) << 3;
    const int ln = tid >> 1, lk = (tid & 1) << 3;

    const float* Ald = A + (size_t)(n0 + ln) * DV + lk;
    const float* Bld = Bm + (size_t)(m0 + ln) * DV + lk;
    float4 ax = *(const float4*)(Ald), ay = *(const float4*)(Ald + 4);
    float4 bx = *(const float4*)(Bld), by = *(const float4*)(Bld + 4);

    u64t acc2[8][4];
    u64t zero2; PACK2(zero2, 0u);
#pragma unroll
    for (int i = 0; i < 8; ++i)
#pragma unroll
        for (int jp = 0; jp < 4; ++jp) acc2[i][jp] = zero2;

    int buf = 0;
#pragma unroll
    for (int m = 0; m < 4; ++m) {
        Xs[0][lk + m][ln] = (&ax.x)[m];   Xs[0][lk + 4 + m][ln] = (&ay.x)[m];
        Ws2[0][lk + m][ln] = (&bx.x)[m];  Ws2[0][lk + 4 + m][ln] = (&by.x)[m];
    }
    __syncthreads();

    const int NKT = DV / GBK;
    for (int kt = 0; kt < NKT; ++kt) {
        if (kt + 1 < NKT) {
            const float* An = Ald + (kt + 1) * GBK;
            const float* Bn = Bld + (kt + 1) * GBK;
            ax = *(const float4*)(An); ay = *(const float4*)(An + 4);
            bx = *(const float4*)(Bn); by = *(const float4*)(Bn + 4);
        }
#pragma unroll
        for (int kk = 0; kk < GBK; ++kk) {
            float av[8];
            *(float4*)&av[0] = *(const float4*)&Xs[buf][kk][ty];
            *(float4*)&av[4] = *(const float4*)&Xs[buf][kk][ty + 4];
            ulonglong2 q0 = *(const ulonglong2*)&Ws2[buf][kk][tx];
            ulonglong2 q1 = *(const ulonglong2*)&Ws2[buf][kk][tx + 4];
            u64t bv2[4] = {q0.x, q0.y, q1.x, q1.y};
#pragma unroll
            for (int i = 0; i < 8; ++i) {
                u64t a2; PACK2(a2, __float_as_uint(av[i]));
#pragma unroll
                for (int jp = 0; jp < 4; ++jp) FFMA2(acc2[i][jp], a2, bv2[jp]);
            }
        }
        if (kt + 1 < NKT) {
            buf ^= 1;
            __syncthreads();
#pragma unroll
            for (int m = 0; m < 4; ++m) {
                Xs[buf][lk + m][ln] = (&ax.x)[m];   Xs[buf][lk + 4 + m][ln] = (&ay.x)[m];
                Ws2[buf][lk + m][ln] = (&bx.x)[m];  Ws2[buf][lk + 4 + m][ln] = (&by.x)[m];
            }
            __syncthreads();
        }
    }
    float4 bb0 = *(const float4*)(bias + m0 + tx);
    float4 bb1 = *(const float4*)(bias + m0 + tx + 4);
    float bvv[8] = {bb0.x, bb0.y, bb0.z, bb0.w, bb1.x, bb1.y, bb1.z, bb1.w};
#pragma unroll
    for (int i = 0; i < 8; ++i) {
        float o[8];
#pragma unroll
        for (int jp = 0; jp < 4; ++jp) {
            unsigned lo, hi;
            UNPACK2(lo, hi, acc2[i][jp]);
            o[2 * jp]     = __uint_as_float(lo) + bvv[2 * jp];
            o[2 * jp + 1] = __uint_as_float(hi) + bvv[2 * jp + 1];
        }
        float* cp = g_xp + (size_t)(n0 + ty + i) * R4H + m0 + tx;
        *(float4*)cp = *(float4*)&o[0];
        *(float4*)(cp + 4) = *(float4*)&o[4];
    }
}

// ---------------------------------------------------------------- LSTM
__global__ void __launch_bounds__(NTH, 1)
lstm_kernel(const float* __restrict__ c0, const float* __restrict__ W_hh,
            const float* __restrict__ b_hh, float* __restrict__ out) {
    extern __shared__ __align__(16) unsigned char smem_raw[];
    uint4* Wq = reinterpret_cast<uint4*>(smem_raw);
    float* pre_part = reinterpret_cast<float*>(smem_raw + (size_t)ROWS * HV * 2);

    const int tid = threadIdx.x, cta = blockIdx.x;
    const int j0 = cta * JPC;
    int J = HV - j0; if (J > JPC) J = JPC; if (J < 0) J = 0;

    // stage W_hh slice -> SMEM fp16, vectorized (uint4 = 8 halves)
    for (int u = tid; u < ROWS * 256; u += NTH) {
        int rl = u >> 8, rem = u & 255;
        int jl = rl >> 2, gate = rl & 3;
        uint4 v = make_uint4(0, 0, 0, 0);
        if (jl < J) {
            const float* wp = W_hh + ((size_t)gate * HV + j0 + jl) * HV + rem * 8;
            v = pack8(*(const float4*)wp, *(const float4*)(wp + 4));
        }
        Wq[u] = v;
    }

    const int warp = tid >> 5, lane = tid & 31;
    const int grp = warp >> 1, khalf = warp & 1;
    const int kb = khalf << 10;
    const int rbase = grp * JPC;

    float c_val = 0.f, b_r[4] = {0.f, 0.f, 0.f, 0.f};
    if (tid < J) {
        c_val = c0[j0 + tid];
#pragma unroll
        for (int g = 0; g < 4; ++g) b_r[g] = b_hh[g * HV + j0 + tid];
    }
    float xp_r[4] = {0.f, 0.f, 0.f, 0.f};
    if (tid < J) {
#pragma unroll
        for (int g = 0; g < 4; ++g)
            xp_r[g] = __ldcg(&g_xp[(size_t)g * HV + j0 + tid]);
    }
    __syncthreads();

    const size_t wbase = (size_t)rbase * 256 + (size_t)khalf * 128 + lane;
    volatile unsigned int* barp = &g_bar;
    const __half2 hz = __float2half2_rn(0.f);

    for (int t = 0; t < STEPS; ++t) {
        const int p = t & 1;

        // ---- h (fp16) -> registers: 4x LDG.128 (L2)
        uint4 hq[4];
        {
            const uint4* hb4 = reinterpret_cast<const uint4*>(&g_hh[p][kb]) + lane;
#pragma unroll
            for (int it = 0; it < 4; ++it) hq[it] = __ldcg(hb4 + it * 32);
        }

        __half2 acc[JPC][4];
#pragma unroll
        for (int r = 0; r < JPC; ++r)
#pragma unroll
            for (int s = 0; s < 4; ++s) acc[r][s] = hz;

#pragma unroll
        for (int it = 0; it < 4; ++it) {
#pragma unroll
            for (int r = 0; r < JPC; ++r) {
                uint4 w = Wq[wbase + (size_t)r * 256 + it * 32];
                acc[r][0] = __hfma2(u2h(w.x), u2h(hq[it].x), acc[r][0]);
                acc[r][1] = __hfma2(u2h(w.y), u2h(hq[it].y), acc[r][1]);
                acc[r][2] = __hfma2(u2h(w.z), u2h(hq[it].z), acc[r][2]);
                acc[r][3] = __hfma2(u2h(w.w), u2h(hq[it].w), acc[r][3]);
            }
        }
#pragma unroll
        for (int r = 0; r < JPC; ++r) {
            float2 f0 = __half22float2(acc[r][0]);
            float2 f1 = __half22float2(acc[r][1]);
            float2 f2 = __half22float2(acc[r][2]);
            float2 f3 = __half22float2(acc[r][3]);
            float v = ((f0.x + f0.y) + (f1.x + f1.y)) +
                      ((f2.x + f2.y) + (f3.x + f3.y));
            v += __shfl_xor_sync(~0u, v, 16);
            v += __shfl_xor_sync(~0u, v, 8);
            v += __shfl_xor_sync(~0u, v, 4);
            v += __shfl_xor_sync(~0u, v, 2);
            v += __shfl_xor_sync(~0u, v, 1);
            if (lane == 0) pre_part[khalf * ROWS + rbase + r] = v;
        }
        __syncthreads();   // #1: pre_part ready for warp 0

        const unsigned tgt = (unsigned)(t + 1) * GRID;
        if (warp == 0) {
            float h_n = 0.f, f_t = 0.f, i_t = 0.f;
            if (tid < J) {
                const int rl = tid << 2;
                float pi = xp_r[0] + b_r[0] + pre_part[rl + 0] + pre_part[ROWS + rl + 0];
                float pf = xp_r[1] + b_r[1] + pre_part[rl + 1] + pre_part[ROWS + rl + 1];
                float po = xp_r[2] + b_r[2] + pre_part[rl + 2] + pre_part[ROWS + rl + 2];
                float pg = xp_r[3] + b_r[3] + pre_part[rl + 3] + pre_part[ROWS + rl + 3];
                i_t = __fdividef(1.0f, 1.0f + __expf(-pi));
                f_t = __fdividef(1.0f, 1.0f + __expf(-pf));
                float o_t = __fdividef(1.0f, 1.0f + __expf(-po));
                float g_t = __fdividef(2.0f, 1.0f + __expf(-2.0f * pg)) - 1.0f;
                c_val = c_val * f_t + i_t * g_t;
                float tc = __fdividef(2.0f, 1.0f + __expf(-2.0f * c_val)) - 1.0f;
                h_n = o_t * tc;
                g_hh[p ^ 1][j0 + tid] = __float2half(h_n);   // ONLY store before fence
            }
            __syncwarp();                 // warp-scope mem sync: lane0 observes h stores
            if (lane == 0) {
                __threadfence();          // drains just the tiny h store (cumulative)
                atomicAdd(&g_bar, 1u);    // REDG arrive
            }
            if (tid < J) {                // off the critical path now
                size_t oi = (size_t)t * HV + j0 + tid;
                out[oi] = h_n;
                out[OUTSTRIDE + oi] = f_t;
                out[2 * OUTSTRIDE + oi] = i_t;
                if (t + 1 < STEPS) {
#pragma unroll
                    for (int g = 0; g < 4; ++g)
                        xp_r[g] = __ldcg(&g_xp[(size_t)(t + 1) * R4H + g * HV + j0 + tid]);
                }
            }
        }
        // single spinner per CTA (R5-proven), broadcast via one bar
        if (tid == 0) {
            while (*barp < tgt) {}
            __threadfence();
        }
        __syncthreads();   // #2: release all warps; also fences pre_part reuse
    }
}

extern "C" void kernel_launch(void* const* d_in, const int* in_sizes, int n_in,
                              void* d_out, int out_size) {
    const float* input_ = (const float*)d_in[0];
    const float* h0 = (const float*)d_in[1];
    const float* c0 = (const float*)d_in[2];
    const float* W_ih = (const float*)d_in[3];
    const float* b_ih = (const float*)d_in[4];
    const float* W_hh = (const float*)d_in[5];
    const float* b_hh = (const float*)d_in[6];
    float* out = (float*)d_out;

    static int smem_set = 0;
    if (!smem_set) {
        cudaFuncSetAttribute(lstm_kernel, cudaFuncAttributeMaxDynamicSharedMemorySize,
                             LSTM_SMEM);
        smem_set = 1;
    }

    gemm_xp<<<dim3(R4H / 128, STEPS / 128), 256>>>(input_, W_ih, b_ih, h0);
    lstm_kernel<<<GRID, NTH, LSTM_SMEM>>>(c0, W_hh, b_hh, out);
}